// round 1
// baseline (speedup 1.0000x reference)
#include <cuda_runtime.h>
#include <cuda_bf16.h>
#include <float.h>
#include <math.h>

#define NUM_CLASSES 13
#define C1 (NUM_CLASSES + 1)   // 14
#define Bn 64
#define Qn 900
#define Tn 128
#define NT 256

// ---- scratch (static device globals; no allocation allowed) ----
__device__ float  g_cost[Bn * Tn * Qn];   // cost[b][t][q]  (transposed layout, row = target)
__device__ float  g_lse[Bn * Qn];         // logsumexp per (b,q)
__device__ int    g_pred[Bn * Tn];        // query index assigned to target t
__device__ double g_partial[Bn];          // per-image loss

// ============================================================================
// 1) Cost matrix: C[b][t][q] = -softmax(pc[b,q])[label[b,t]] + L1(pb[b,q], tb[b,t])
// ============================================================================
__global__ __launch_bounds__(NT) void cost_kernel(
    const float* __restrict__ pc,   // [B,Q,14]
    const float* __restrict__ pb,   // [B,Q,4]
    const int*   __restrict__ lab,  // [B,T]
    const float* __restrict__ tb)   // [B,T,4]
{
    int b = blockIdx.y;
    int q = blockIdx.x * blockDim.x + threadIdx.x;

    __shared__ float s_tb[Tn * 4];
    __shared__ int   s_lab[Tn];
    for (int i = threadIdx.x; i < Tn * 4; i += NT) s_tb[i] = tb[b * Tn * 4 + i];
    for (int i = threadIdx.x; i < Tn; i += NT)     s_lab[i] = lab[b * Tn + i];
    __syncthreads();
    if (q >= Qn) return;

    const float* lg = pc + (size_t)(b * Qn + q) * C1;
    float m = lg[0];
    #pragma unroll
    for (int c = 1; c < C1; c++) m = fmaxf(m, lg[c]);
    float e[C1]; float se = 0.f;
    #pragma unroll
    for (int c = 0; c < C1; c++) { e[c] = __expf(lg[c] - m); se += e[c]; }
    float inv = 1.0f / se;
    g_lse[b * Qn + q] = m + logf(se);

    const float4 pbq = *reinterpret_cast<const float4*>(pb + (size_t)(b * Qn + q) * 4);

    float* crow = g_cost + (size_t)b * Tn * Qn + q;
    #pragma unroll 4
    for (int t = 0; t < Tn; t++) {
        float cb = fabsf(pbq.x - s_tb[t * 4 + 0]) + fabsf(pbq.y - s_tb[t * 4 + 1])
                 + fabsf(pbq.z - s_tb[t * 4 + 2]) + fabsf(pbq.w - s_tb[t * 4 + 3]);
        float cc = -e[s_lab[t]] * inv;
        crow[(size_t)t * Qn] = cb + cc;
    }
}

// ============================================================================
// 2) Hungarian (Jonker-Volgenant, e-maxx form) — one CTA per image.
//    rows = targets (128), cols = queries (900). Duals in double (ref uses f64).
// ============================================================================
__global__ __launch_bounds__(NT) void hungarian_kernel()
{
    int b = blockIdx.x;
    int tid = threadIdx.x;

    __shared__ double u[Tn + 1];
    __shared__ double v[Qn + 1];
    __shared__ double minv[Qn + 1];
    __shared__ int    p[Qn + 1];
    __shared__ int    way[Qn + 1];
    __shared__ unsigned char used[Qn + 1];
    __shared__ double s_rv[NT];
    __shared__ int    s_ri[NT];
    __shared__ int    s_j0, s_i0;

    for (int j = tid; j <= Qn; j += NT) { v[j] = 0.0; p[j] = 0; }
    for (int i = tid; i <= Tn; i += NT) u[i] = 0.0;
    __syncthreads();

    const float* cost = g_cost + (size_t)b * Tn * Qn;

    for (int i = 1; i <= Tn; i++) {
        if (tid == 0) { p[0] = i; s_j0 = 0; }
        for (int j = tid; j <= Qn; j += NT) { minv[j] = DBL_MAX; used[j] = 0; }
        __syncthreads();

        while (true) {
            if (tid == 0) { int j0 = s_j0; used[j0] = 1; s_i0 = p[j0]; }
            __syncthreads();
            int i0 = s_i0;
            int j0 = s_j0;
            double ui0 = u[i0];
            const float* crow = cost + (size_t)(i0 - 1) * Qn;

            // scan free columns: update minv/way, track local (min, idx)
            double lv = DBL_MAX; int li = Qn + 1;
            for (int j = tid + 1; j <= Qn; j += NT) {
                if (!used[j]) {
                    double cur = (double)crow[j - 1] - ui0 - v[j];
                    if (cur < minv[j]) { minv[j] = cur; way[j] = j0; }
                    double mv = minv[j];
                    if (mv < lv) { lv = mv; li = j; }   // strided asc j => first idx kept
                }
            }
            s_rv[tid] = lv; s_ri[tid] = li;
            __syncthreads();
            // tree argmin, lowest-index tie-break (numpy argmin semantics)
            for (int s = NT / 2; s > 0; s >>= 1) {
                if (tid < s) {
                    double ov = s_rv[tid + s]; int oi = s_ri[tid + s];
                    if (ov < s_rv[tid] || (ov == s_rv[tid] && oi < s_ri[tid])) {
                        s_rv[tid] = ov; s_ri[tid] = oi;
                    }
                }
                __syncthreads();
            }
            int j1 = s_ri[0];
            double delta = s_rv[0];

            // dual updates (distinct p[j] across used j -> race-free)
            for (int j = tid; j <= Qn; j += NT) {
                if (used[j]) { u[p[j]] += delta; v[j] -= delta; }
                else         { minv[j] -= delta; }
            }
            __syncthreads();
            if (tid == 0) s_j0 = j1;
            __syncthreads();
            if (p[j1] == 0) break;
        }

        // augment along alternating path (serial, short)
        if (tid == 0) {
            int j0 = s_j0;
            while (j0) {
                int j1 = way[j0];
                p[j0] = p[j1];
                j0 = j1;
            }
        }
        __syncthreads();
    }

    for (int j = tid + 1; j <= Qn; j += NT) {
        int pi = p[j];
        if (pi > 0) g_pred[b * Tn + pi - 1] = j - 1;
    }
}

// ============================================================================
// 3) Per-image loss: 5*L1_mean + 2*mean(1-GIoU) + weighted CE
// ============================================================================
__device__ __forceinline__ double block_reduce_sum(double val, double* sred)
{
    int tid = threadIdx.x;
    sred[tid] = val;
    __syncthreads();
    for (int s = NT / 2; s > 0; s >>= 1) {
        if (tid < s) sred[tid] += sred[tid + s];
        __syncthreads();
    }
    double r = sred[0];
    __syncthreads();
    return r;
}

__global__ __launch_bounds__(NT) void loss_kernel(
    const float* __restrict__ pc,
    const float* __restrict__ pb,
    const int*   __restrict__ lab,
    const float* __restrict__ tb)
{
    int b = blockIdx.x;
    int tid = threadIdx.x;
    __shared__ int tcl[Qn];
    __shared__ double sred[NT];

    double l1 = 0.0, gsum = 0.0;
    if (tid < Tn) {
        int t = tid;
        int qi = g_pred[b * Tn + t];
        const float4 P = *reinterpret_cast<const float4*>(pb + (size_t)(b * Qn + qi) * 4);
        const float4 G = *reinterpret_cast<const float4*>(tb + (size_t)(b * Tn + t) * 4);
        double px = P.x, py = P.y, pw = P.z, ph = P.w;
        double gx = G.x, gy = G.y, gw = G.z, gh = G.w;
        l1 = fabs(px - gx) + fabs(py - gy) + fabs(pw - gw) + fabs(ph - gh);

        double p0 = px - 0.5 * pw, p1 = py - 0.5 * ph, p2 = px + 0.5 * pw, p3 = py + 0.5 * ph;
        double g0 = gx - 0.5 * gw, g1 = gy - 0.5 * gh, g2 = gx + 0.5 * gw, g3 = gy + 0.5 * gh;
        double a1 = (p2 - p0) * (p3 - p1);
        double a2 = (g2 - g0) * (g3 - g1);
        double iw = fmin(p2, g2) - fmax(p0, g0); iw = iw > 0.0 ? iw : 0.0;
        double ih = fmin(p3, g3) - fmax(p1, g1); ih = ih > 0.0 ? ih : 0.0;
        double inter = iw * ih;
        double uni = a1 + a2 - inter;
        double iou = inter / uni;
        double cw = fmax(p2, g2) - fmin(p0, g0);
        double ch = fmax(p3, g3) - fmin(p1, g1);
        double ac = cw * ch;
        double giou = iou - (ac - uni) / ac;
        gsum = 1.0 - giou;
    }

    for (int q = tid; q < Qn; q += NT) tcl[q] = NUM_CLASSES;
    __syncthreads();
    if (tid < Tn) tcl[g_pred[b * Tn + tid]] = lab[b * Tn + tid];
    __syncthreads();

    double wn = 0.0, ws = 0.0;
    for (int q = tid; q < Qn; q += NT) {
        int c = tcl[q];
        double w = (c == NUM_CLASSES) ? 0.05 : 1.0;
        double nll = (double)g_lse[b * Qn + q] - (double)pc[(size_t)(b * Qn + q) * C1 + c];
        wn += w * nll; ws += w;
    }

    double l1t  = block_reduce_sum(l1, sred);
    double gst  = block_reduce_sum(gsum, sred);
    double wnt  = block_reduce_sum(wn, sred);
    double wst  = block_reduce_sum(ws, sred);

    if (tid == 0) {
        double bbox = 5.0 * (l1t / (Tn * 4.0)) + 2.0 * (gst / Tn);
        g_partial[b] = bbox + wnt / wst;
    }
}

__global__ void finalize_kernel(float* out)
{
    __shared__ double sred[64];
    int tid = threadIdx.x;
    sred[tid] = g_partial[tid];
    __syncthreads();
    for (int s = 32; s > 0; s >>= 1) {
        if (tid < s) sred[tid] += sred[tid + s];
        __syncthreads();
    }
    if (tid == 0) out[0] = (float)(sred[0] / (double)(Bn * Tn));
}

extern "C" void kernel_launch(void* const* d_in, const int* in_sizes, int n_in,
                              void* d_out, int out_size)
{
    const float* pc  = (const float*)d_in[0];   // predicted_class [64,900,14]
    const float* pb  = (const float*)d_in[1];   // predicted_bbox  [64,900,4]
    const int*   lab = (const int*)  d_in[2];   // target_labels   [64,128]
    const float* tb  = (const float*)d_in[3];   // target_boxes    [64,128,4]
    float* out = (float*)d_out;

    dim3 cgrid((Qn + NT - 1) / NT, Bn);
    cost_kernel<<<cgrid, NT>>>(pc, pb, lab, tb);
    hungarian_kernel<<<Bn, NT>>>();
    loss_kernel<<<Bn, NT>>>(pc, pb, lab, tb);
    finalize_kernel<<<1, 64>>>(out);
}